// round 16
// baseline (speedup 1.0000x reference)
#include <cuda_runtime.h>
#include <cuda_bf16.h>

#define NN 10000
#define EE 160000
#define GG 64
#define F_IN 128
#define C1D 128
#define C2D 256
#define C3D 512
#define KCH 5
#define NCLS 10
#define TXW (KCH * F_IN)   // 640
#define NEG_INF (-3.402823466e38f)

typedef __nv_bfloat16 bf16;
typedef __nv_bfloat162 bf162;

// ---------------- scratch (device globals; zero-initialized at load) --------
__device__ int   g_cnt_in[NN];
__device__ int   g_cnt_out[NN];
__device__ int   g_cursor[NN];
__device__ int   g_bar;            // spin barrier for fused dinv+scan (reset in pool tail)
__device__ int   g_bsum[40];
__device__ int   g_row_ptr[NN + 1];
__device__ int   g_col[EE];
__device__ float g_dinv_cheb[NN];
__device__ float g_dinv_gcn[NN];
__device__ float g_e[NN];          // gate logits (zeroed in k_fill, filled by GEMM3 epilogue)
__device__ float g_TX[(size_t)NN * TXW];
__device__ float g_bufA[(size_t)NN * C3D];
__device__ float g_bufB[(size_t)NN * C2D];

// bf16 hi/lo split operands
__device__ __align__(16) bf16 g_txh[(size_t)NN * TXW];
__device__ __align__(16) bf16 g_txl[(size_t)NN * TXW];
__device__ __align__(16) bf16 g_axh[(size_t)NN * C2D];
__device__ __align__(16) bf16 g_axl[(size_t)NN * C2D];
#define WC_OFF 0
#define W1_OFF (C1D * TXW)
#define W2_OFF (W1_OFF + C2D * C1D)
#define W_TOT  (W2_OFF + C3D * C2D)
__device__ __align__(16) bf16 g_wth[W_TOT];
__device__ __align__(16) bf16 g_wtl[W_TOT];

// ---------------- helpers ---------------------------------------------------
__device__ __forceinline__ void split_bf16(float v, bf16& hi, bf16& lo) {
    hi = __float2bfloat16(v);
    lo = __float2bfloat16(v - __bfloat162float(hi));
}

__device__ __forceinline__ void write_split4(bf16* hbase, bf16* lbase, size_t idx, float4 v) {
    bf16 h0, l0, h1, l1, h2, l2, h3, l3;
    split_bf16(v.x, h0, l0); split_bf16(v.y, h1, l1);
    split_bf16(v.z, h2, l2); split_bf16(v.w, h3, l3);
    *(bf162*)(hbase + idx)     = bf162(h0, h1);
    *(bf162*)(hbase + idx + 2) = bf162(h2, h3);
    *(bf162*)(lbase + idx)     = bf162(l0, l1);
    *(bf162*)(lbase + idx + 2) = bf162(l2, l3);
}

__device__ __forceinline__ void cp16(void* sm, const void* gm) {
    unsigned sa = (unsigned)__cvta_generic_to_shared(sm);
    asm volatile("cp.async.cg.shared.global [%0], [%1], 16;" :: "r"(sa), "l"(gm));
}

// ---------------- fused prep: copy_x + 3 weight splits + edge counting -------
#define PREP_CX   1250
#define PREP_WC   (PREP_CX + 320)
#define PREP_W1   (PREP_WC + 128)
#define PREP_W2   (PREP_W1 + 512)
#define PREP_CNT  (PREP_W2 + 625)
__global__ void k_prep(const float* __restrict__ x, const float* __restrict__ Wc,
                       const float* __restrict__ W1, const float* __restrict__ W2,
                       const int* __restrict__ ei) {
    int b = blockIdx.x, tid = threadIdx.x;
    if (b < PREP_CX) {
        int idx = b * 256 + tid;
        int n = idx >> 5, j = idx & 31;
        float4 v = ((const float4*)x)[(size_t)n * 32 + j];
        size_t o = (size_t)n * TXW + j * 4;
        *((float4*)(g_TX + o)) = v;
        write_split4(g_txh, g_txl, o, v);
    } else if (b < PREP_WC) {
        int idx = (b - PREP_CX) * 256 + tid;
        int k = idx / C1D, n = idx - k * C1D;
        bf16 hi, lo; split_bf16(Wc[idx], hi, lo);
        g_wth[WC_OFF + (size_t)n * TXW + k] = hi;
        g_wtl[WC_OFF + (size_t)n * TXW + k] = lo;
    } else if (b < PREP_W1) {
        int idx = (b - PREP_WC) * 256 + tid;
        int k = idx / C2D, n = idx - k * C2D;
        bf16 hi, lo; split_bf16(W1[idx], hi, lo);
        g_wth[W1_OFF + (size_t)n * C1D + k] = hi;
        g_wtl[W1_OFF + (size_t)n * C1D + k] = lo;
    } else if (b < PREP_W2) {
        int idx = (b - PREP_W1) * 256 + tid;
        int k = idx / C3D, n = idx - k * C3D;
        bf16 hi, lo; split_bf16(W2[idx], hi, lo);
        g_wth[W2_OFF + (size_t)n * C2D + k] = hi;
        g_wtl[W2_OFF + (size_t)n * C2D + k] = lo;
    } else {
        int e = (b - PREP_W2) * 256 + tid;
        if (e < EE) {
            atomicAdd(&g_cnt_out[ei[e]], 1);
            atomicAdd(&g_cnt_in[ei[EE + e]], 1);
        }
    }
}

// ---------------- fused dinv + scan (40 blocks, spin barrier) ----------------
__global__ void k_dinv_scan() {
    __shared__ int red[256];
    __shared__ int sm_bs[40];
    __shared__ int sm_ws[8];
    int tid = threadIdx.x, lane = tid & 31, warp = tid >> 5;
    int i = blockIdx.x * 256 + tid;

    // phase 1: dinv + block sums
    int ci = 0;
    if (i < NN) {
        int oc = g_cnt_out[i];
        ci = g_cnt_in[i];
        g_dinv_cheb[i] = oc > 0 ? rsqrtf((float)oc) : 0.f;
        g_dinv_gcn[i]  = rsqrtf((float)(ci + 1));
    }
    red[tid] = ci;
    __syncthreads();
    #pragma unroll
    for (int s = 128; s > 0; s >>= 1) {
        if (tid < s) red[tid] += red[tid + s];
        __syncthreads();
    }
    if (tid == 0) g_bsum[blockIdx.x] = red[0];

    // grid barrier (40 blocks, all resident)
    if (tid == 0) {
        __threadfence();
        atomicAdd(&g_bar, 1);
        while (atomicAdd(&g_bar, 0) < 40) {}
    }
    __syncthreads();

    // phase 2: scan
    if (tid < 40) sm_bs[tid] = g_bsum[tid];
    __syncthreads();
    if (tid == 0) {
        int acc = 0;
        for (int b = 0; b < 40; b++) { int v = sm_bs[b]; sm_bs[b] = acc; acc += v; }
    }
    __syncthreads();
    int v = (i < NN) ? g_cnt_in[i] : 0;
    int inc = v;
    #pragma unroll
    for (int o = 1; o < 32; o <<= 1) {
        int t = __shfl_up_sync(0xffffffffu, inc, o);
        if (lane >= o) inc += t;
    }
    if (lane == 31) sm_ws[warp] = inc;
    __syncthreads();
    if (tid == 0) {
        int acc = 0;
        #pragma unroll
        for (int w = 0; w < 8; w++) { int t = sm_ws[w]; sm_ws[w] = acc; acc += t; }
    }
    __syncthreads();
    int excl = sm_bs[blockIdx.x] + sm_ws[warp] + inc - v;
    if (i < NN) g_row_ptr[i] = excl;
    if (i == NN - 1) g_row_ptr[NN] = excl + v;
}

__global__ void k_fill(const int* __restrict__ ei) {
    int e = blockIdx.x * blockDim.x + threadIdx.x;
    if (e < NN) g_e[e] = 0.f;      // pre-zero gate logits for GEMM3 epilogue
    if (e >= EE) return;
    int s = ei[e];
    int d = ei[EE + e];
    int pos = g_row_ptr[d] + atomicAdd(&g_cursor[d], 1);
    g_col[pos] = s;
}

// ---------------- Cheb gather (static, two-phase MLP 8, dst factor folded) ---
__global__ void k_gather_cheb(int src_off, int dst_off, int tx0_off, int mode, int store_f32) {
    int n = blockIdx.x * 8 + (threadIdx.x >> 5);
    int j = threadIdx.x & 31;
    if (n >= NN) return;
    int beg = g_row_ptr[n], end = g_row_ptr[n + 1];
    float4 acc = {0.f, 0.f, 0.f, 0.f};
    int r = beg;
    for (; r + 8 <= end; r += 8) {
        int   s[8];
        #pragma unroll
        for (int u = 0; u < 8; u++) s[u] = __ldg(&g_col[r + u]);
        float w[8];
        #pragma unroll
        for (int u = 0; u < 8; u++) w[u] = __ldg(&g_dinv_cheb[s[u]]);
        float4 h[8];
        #pragma unroll
        for (int u = 0; u < 8; u++)
            h[u] = *(const float4*)(g_TX + (size_t)s[u] * TXW + src_off + j * 4);
        #pragma unroll
        for (int u = 0; u < 8; u++) {
            acc.x += w[u] * h[u].x; acc.y += w[u] * h[u].y;
            acc.z += w[u] * h[u].z; acc.w += w[u] * h[u].w;
        }
    }
    for (; r < end; r++) {
        int s   = __ldg(&g_col[r]);
        float w = __ldg(&g_dinv_cheb[s]);
        float4 h = *(const float4*)(g_TX + (size_t)s * TXW + src_off + j * 4);
        acc.x += w * h.x; acc.y += w * h.y; acc.z += w * h.z; acc.w += w * h.w;
    }
    float f = -g_dinv_cheb[n] * (mode ? 2.f : 1.f);
    float4 res;
    if (mode) {
        float4 t0 = *(const float4*)(g_TX + (size_t)n * TXW + tx0_off + j * 4);
        res.x = fmaf(f, acc.x, -t0.x); res.y = fmaf(f, acc.y, -t0.y);
        res.z = fmaf(f, acc.z, -t0.z); res.w = fmaf(f, acc.w, -t0.w);
    } else {
        res.x = f * acc.x; res.y = f * acc.y; res.z = f * acc.z; res.w = f * acc.w;
    }
    size_t o = (size_t)n * TXW + dst_off + j * 4;
    if (store_f32) *(float4*)(g_TX + o) = res;
    write_split4(g_txh, g_txl, o, res);
}

// ---------------- GCN gather in INPUT space (dst factor folded) ---------------
template <int C>
__global__ void k_gather_gcn_pre(const float* __restrict__ h,
                                 bf16* __restrict__ oh, bf16* __restrict__ ol) {
    constexpr int TPN = C / 4;
    constexpr int NPB = 256 / TPN;
    int local = threadIdx.x / TPN;
    int j     = threadIdx.x % TPN;
    int n = blockIdx.x * NPB + local;
    if (n >= NN) return;
    const float4* h4 = (const float4*)h;
    int beg = g_row_ptr[n], end = g_row_ptr[n + 1];
    float4 acc = {0.f, 0.f, 0.f, 0.f};
    int r = beg;
    for (; r + 8 <= end; r += 8) {
        int   s[8];
        #pragma unroll
        for (int u = 0; u < 8; u++) s[u] = __ldg(&g_col[r + u]);
        float w[8];
        #pragma unroll
        for (int u = 0; u < 8; u++) w[u] = __ldg(&g_dinv_gcn[s[u]]);
        float4 hv[8];
        #pragma unroll
        for (int u = 0; u < 8; u++) hv[u] = h4[(size_t)s[u] * TPN + j];
        #pragma unroll
        for (int u = 0; u < 8; u++) {
            acc.x += w[u] * hv[u].x; acc.y += w[u] * hv[u].y;
            acc.z += w[u] * hv[u].z; acc.w += w[u] * hv[u].w;
        }
    }
    for (; r < end; r++) {
        int s   = __ldg(&g_col[r]);
        float w = __ldg(&g_dinv_gcn[s]);
        float4 hv = h4[(size_t)s * TPN + j];
        acc.x += w * hv.x; acc.y += w * hv.y; acc.z += w * hv.z; acc.w += w * hv.w;
    }
    float di = g_dinv_gcn[n];
    float sw = di * di;
    float4 self = h4[(size_t)n * TPN + j];
    float4 res;
    res.x = fmaf(di, acc.x, sw * self.x);
    res.y = fmaf(di, acc.y, sw * self.y);
    res.z = fmaf(di, acc.z, sw * self.z);
    res.w = fmaf(di, acc.w, sw * self.w);
    write_split4(oh, ol, (size_t)n * C + j * 4, res);
}

// ---------------- bf16x3 tensor-core GEMM, double-buffered cp.async -----------
// flags: bit0 bias, bit1 relu, bit2 accumulate gate logits into g_e (wgate != null)
#define GBM 128
#define GBN 64
#define GBK 32
#define SPAD 8
#define ROWW (GBK + SPAD)
#define A_ELEMS (GBM * ROWW)
#define B_ELEMS (GBN * ROWW)
#define STAGE_ELEMS (2 * A_ELEMS + 2 * B_ELEMS)
#define GEMM_SMEM (2 * STAGE_ELEMS * 2)

__device__ __forceinline__ void mma_bf16(float c[4], unsigned a0, unsigned a1,
                                         unsigned a2, unsigned a3,
                                         unsigned b0, unsigned b1) {
    asm volatile(
        "mma.sync.aligned.m16n8k16.row.col.f32.bf16.bf16.f32 "
        "{%0,%1,%2,%3}, {%4,%5,%6,%7}, {%8,%9}, {%0,%1,%2,%3};"
        : "+f"(c[0]), "+f"(c[1]), "+f"(c[2]), "+f"(c[3])
        : "r"(a0), "r"(a1), "r"(a2), "r"(a3), "r"(b0), "r"(b1));
}

__global__ __launch_bounds__(256, 2)
void k_gemm_tc(const bf16* __restrict__ Agh, const bf16* __restrict__ Agl,
               const bf16* __restrict__ Bgh, const bf16* __restrict__ Bgl,
               const float* __restrict__ bias, const float* __restrict__ wgate,
               float* __restrict__ Cf,
               int M, int Kd, int Nd, int flags) {
    extern __shared__ bf16 sm[];
    int tid = threadIdx.x;
    int wid = tid >> 5, lane = tid & 31;
    int wm = wid >> 1, wn = wid & 1;
    int g = lane >> 2, tg = lane & 3;
    int brow = blockIdx.y * GBM;
    int bcol = blockIdx.x * GBN;

    float acc[2][4][4];
    #pragma unroll
    for (int a = 0; a < 2; a++)
        #pragma unroll
        for (int b = 0; b < 4; b++)
            #pragma unroll
            for (int c = 0; c < 4; c++) acc[a][b][c] = 0.f;

    int sr = tid >> 2;
    int sq = (tid & 3) * 8;

    auto AH = [&](int st) { return sm + st * STAGE_ELEMS; };
    auto AL = [&](int st) { return sm + st * STAGE_ELEMS + A_ELEMS; };
    auto BH = [&](int st) { return sm + st * STAGE_ELEMS + 2 * A_ELEMS; };
    auto BL = [&](int st) { return sm + st * STAGE_ELEMS + 2 * A_ELEMS + B_ELEMS; };

    auto load_tile = [&](int k0, int st) {
        #pragma unroll
        for (int i = 0; i < 2; i++) {
            int r = sr + i * 64;
            int gr = min(brow + r, M - 1);
            size_t go = (size_t)gr * Kd + k0 + sq;
            cp16(AH(st) + r * ROWW + sq, Agh + go);
            cp16(AL(st) + r * ROWW + sq, Agl + go);
        }
        size_t go = (size_t)(bcol + sr) * Kd + k0 + sq;
        cp16(BH(st) + sr * ROWW + sq, Bgh + go);
        cp16(BL(st) + sr * ROWW + sq, Bgl + go);
    };

    int nt = Kd / GBK;
    load_tile(0, 0);
    asm volatile("cp.async.commit_group;");

    for (int t = 0; t < nt; t++) {
        if (t + 1 < nt) {
            load_tile((t + 1) * GBK, (t + 1) & 1);
            asm volatile("cp.async.commit_group;");
            asm volatile("cp.async.wait_group 1;");
        } else {
            asm volatile("cp.async.wait_group 0;");
        }
        __syncthreads();

        int st = t & 1;
        const bf16* ah_b = AH(st);
        const bf16* al_b = AL(st);
        const bf16* bh_b = BH(st);
        const bf16* bl_b = BL(st);

        #pragma unroll
        for (int ks = 0; ks < 2; ks++) {
            int kb = ks * 16;
            unsigned ah[2][4], al[2][4];
            #pragma unroll
            for (int mf = 0; mf < 2; mf++) {
                int row = wm * 32 + mf * 16;
                ah[mf][0] = *(const unsigned*)(ah_b + (row + g) * ROWW + kb + 2 * tg);
                ah[mf][1] = *(const unsigned*)(ah_b + (row + g + 8) * ROWW + kb + 2 * tg);
                ah[mf][2] = *(const unsigned*)(ah_b + (row + g) * ROWW + kb + 2 * tg + 8);
                ah[mf][3] = *(const unsigned*)(ah_b + (row + g + 8) * ROWW + kb + 2 * tg + 8);
                al[mf][0] = *(const unsigned*)(al_b + (row + g) * ROWW + kb + 2 * tg);
                al[mf][1] = *(const unsigned*)(al_b + (row + g + 8) * ROWW + kb + 2 * tg);
                al[mf][2] = *(const unsigned*)(al_b + (row + g) * ROWW + kb + 2 * tg + 8);
                al[mf][3] = *(const unsigned*)(al_b + (row + g + 8) * ROWW + kb + 2 * tg + 8);
            }
            #pragma unroll
            for (int nf = 0; nf < 4; nf++) {
                int nn = wn * 32 + nf * 8 + g;
                unsigned bh0 = *(const unsigned*)(bh_b + nn * ROWW + kb + 2 * tg);
                unsigned bh1 = *(const unsigned*)(bh_b + nn * ROWW + kb + 2 * tg + 8);
                unsigned bl0 = *(const unsigned*)(bl_b + nn * ROWW + kb + 2 * tg);
                unsigned bl1 = *(const unsigned*)(bl_b + nn * ROWW + kb + 2 * tg + 8);
                #pragma unroll
                for (int mf = 0; mf < 2; mf++) {
                    mma_bf16(acc[mf][nf], ah[mf][0], ah[mf][1], ah[mf][2], ah[mf][3], bh0, bh1);
                    mma_bf16(acc[mf][nf], ah[mf][0], ah[mf][1], ah[mf][2], ah[mf][3], bl0, bl1);
                    mma_bf16(acc[mf][nf], al[mf][0], al[mf][1], al[mf][2], al[mf][3], bh0, bh1);
                }
            }
        }
        __syncthreads();
    }

    #pragma unroll
    for (int mf = 0; mf < 2; mf++) {
        int gr0 = brow + wm * 32 + mf * 16 + g;
        float lg0 = 0.f, lg1 = 0.f;        // gate-logit partials for rows gr0, gr0+8
        #pragma unroll
        for (int nf = 0; nf < 4; nf++) {
            int gc = bcol + wn * 32 + nf * 8 + 2 * tg;
            float b0 = 0.f, b1 = 0.f;
            if (flags & 1) { b0 = bias[gc]; b1 = bias[gc + 1]; }
            float v0 = acc[mf][nf][0] + b0;
            float v1 = acc[mf][nf][1] + b1;
            float v2 = acc[mf][nf][2] + b0;
            float v3 = acc[mf][nf][3] + b1;
            if (flags & 2) {
                v0 = fmaxf(v0, 0.f); v1 = fmaxf(v1, 0.f);
                v2 = fmaxf(v2, 0.f); v3 = fmaxf(v3, 0.f);
            }
            if (flags & 4) {
                float w0 = wgate[gc], w1 = wgate[gc + 1];
                lg0 += v0 * w0 + v1 * w1;
                lg1 += v2 * w0 + v3 * w1;
            }
            if (gr0 < M)     *(float2*)(Cf + (size_t)gr0 * Nd + gc)       = make_float2(v0, v1);
            if (gr0 + 8 < M) *(float2*)(Cf + (size_t)(gr0 + 8) * Nd + gc) = make_float2(v2, v3);
        }
        if (flags & 4) {
            // reduce across the 4 tg lanes (same row, different cols)
            #pragma unroll
            for (int o = 1; o < 4; o <<= 1) {
                lg0 += __shfl_xor_sync(0xffffffffu, lg0, o);
                lg1 += __shfl_xor_sync(0xffffffffu, lg1, o);
            }
            if (tg == 0) {
                if (gr0 < M)     atomicAdd(&g_e[gr0], lg0);
                if (gr0 + 8 < M) atomicAdd(&g_e[gr0 + 8], lg1);
            }
        }
    }
}

// ---------------- fused attention pooling + FC + log_softmax ------------------
// logits precomputed in g_e by GEMM3 epilogue
__global__ void k_pool_fused(const int* __restrict__ batch, const float* __restrict__ h,
                             const float* __restrict__ Wfc, const float* __restrict__ bfc,
                             float* __restrict__ out) {
    if (blockIdx.x >= GG) {
        int i = (blockIdx.x - GG) * 256 + threadIdx.x;
        if (i < NN) { g_cnt_in[i] = 0; g_cnt_out[i] = 0; g_cursor[i] = 0; }
        if (blockIdx.x == GG && threadIdx.x == 0) g_bar = 0;
        return;
    }
    int g = blockIdx.x;
    int tid = threadIdx.x, lane = tid & 31, warp = tid >> 5;
    __shared__ float sm_part[8][C3D / 4];
    __shared__ float sm_pool[C3D];
    __shared__ float sm_w[64];
    __shared__ float sm_scalar[3];
    __shared__ int   sm_range[2];

    if (tid == 0) {
        int lo = 0, hi = NN;
        while (lo < hi) { int mid = (lo + hi) >> 1; if (batch[mid] < g) lo = mid + 1; else hi = mid; }
        sm_range[0] = lo;
        lo = 0; hi = NN;
        while (lo < hi) { int mid = (lo + hi) >> 1; if (batch[mid] < g + 1) lo = mid + 1; else hi = mid; }
        sm_range[1] = lo;
        sm_scalar[0] = NEG_INF; sm_scalar[1] = 0.f;
    }
    __syncthreads();
    int start = sm_range[0], end = sm_range[1];

    float part[16];
    #pragma unroll
    for (int k = 0; k < 16; k++) part[k] = 0.f;

    for (int base = start; base < end; base += 64) {
        int cnt = min(64, end - base);
        if (tid < cnt) sm_w[tid] = g_e[base + tid];
        __syncthreads();
        if (warp == 0) {
            float v = NEG_INF;
            for (int i = lane; i < cnt; i += 32) v = fmaxf(v, sm_w[i]);
            #pragma unroll
            for (int o = 16; o; o >>= 1) v = fmaxf(v, __shfl_xor_sync(0xffffffffu, v, o));
            if (lane == 0) {
                float oldm = sm_scalar[0];
                float newm = fmaxf(oldm, v);
                sm_scalar[2] = expf(oldm - newm);
                sm_scalar[0] = newm;
            }
        }
        __syncthreads();
        float newm = sm_scalar[0], r = sm_scalar[2];
        if (tid < cnt) sm_w[tid] = expf(sm_w[tid] - newm);
        __syncthreads();
        if (warp == 0) {
            float v = 0.f;
            for (int i = lane; i < cnt; i += 32) v += sm_w[i];
            #pragma unroll
            for (int o = 16; o; o >>= 1) v += __shfl_xor_sync(0xffffffffu, v, o);
            if (lane == 0) sm_scalar[1] = sm_scalar[1] * r + v;
        }
        #pragma unroll
        for (int k = 0; k < 16; k++) part[k] *= r;
        for (int i = warp; i < cnt; i += 8) {
            float w = sm_w[i];
            const float* hr = h + (size_t)(base + i) * C3D;
            #pragma unroll
            for (int k = 0; k < 16; k++) part[k] = fmaf(w, hr[lane + k * 32], part[k]);
        }
        __syncthreads();
    }

    #pragma unroll
    for (int q = 0; q < 4; q++) {
        #pragma unroll
        for (int k = 0; k < 4; k++)
            sm_part[warp][k * 32 + lane] = part[q * 4 + k];
        __syncthreads();
        if (tid < 128) {
            float s = 0.f;
            #pragma unroll
            for (int w8 = 0; w8 < 8; w8++) s += sm_part[w8][tid];
            sm_pool[q * 128 + tid] = s;
        }
        __syncthreads();
    }

    float s = sm_scalar[1];
    float inv = (s > 0.f) ? 1.f / s : 0.f;
    if (warp == 0) {
        float lg[NCLS];
        #pragma unroll
        for (int c = 0; c < NCLS; c++) {
            float acc = 0.f;
            for (int k = lane; k < C3D; k += 32) acc += sm_pool[k] * Wfc[(size_t)k * NCLS + c];
            #pragma unroll
            for (int o = 16; o; o >>= 1) acc += __shfl_xor_sync(0xffffffffu, acc, o);
            lg[c] = acc * inv + bfc[c];
        }
        if (lane == 0) {
            float m = lg[0];
            #pragma unroll
            for (int c = 1; c < NCLS; c++) m = fmaxf(m, lg[c]);
            float ss = 0.f;
            #pragma unroll
            for (int c = 0; c < NCLS; c++) ss += expf(lg[c] - m);
            float lse = m + logf(ss);
            #pragma unroll
            for (int c = 0; c < NCLS; c++) out[(size_t)g * NCLS + c] = lg[c] - lse;
        }
    }
}

// ---------------- launch ------------------------------------------------------
extern "C" void kernel_launch(void* const* d_in, const int* in_sizes, int n_in,
                              void* d_out, int out_size) {
    const float* x      = (const float*)d_in[0];
    const int*   ei     = (const int*)d_in[1];
    const int*   batch  = (const int*)d_in[2];
    const float* Wcheb  = (const float*)d_in[3];
    const float* bcheb  = (const float*)d_in[4];
    const float* Wg1    = (const float*)d_in[5];
    const float* bg1    = (const float*)d_in[6];
    const float* Wg2    = (const float*)d_in[7];
    const float* bg2    = (const float*)d_in[8];
    const float* wgate  = (const float*)d_in[9];
    const float* Wfc    = (const float*)d_in[11];
    const float* bfc    = (const float*)d_in[12];
    float*       out    = (float*)d_out;

    float *pA, *pB;
    bf16 *ptxh, *ptxl, *paxh, *paxl, *pwh, *pwl;
    cudaGetSymbolAddress((void**)&pA,   g_bufA);
    cudaGetSymbolAddress((void**)&pB,   g_bufB);
    cudaGetSymbolAddress((void**)&ptxh, g_txh);
    cudaGetSymbolAddress((void**)&ptxl, g_txl);
    cudaGetSymbolAddress((void**)&paxh, g_axh);
    cudaGetSymbolAddress((void**)&paxl, g_axl);
    cudaGetSymbolAddress((void**)&pwh,  g_wth);
    cudaGetSymbolAddress((void**)&pwl,  g_wtl);

    static bool attr_set = false;
    if (!attr_set) {
        cudaFuncSetAttribute(k_gemm_tc, cudaFuncAttributeMaxDynamicSharedMemorySize, GEMM_SMEM);
        attr_set = true;
    }

    const int T = 256;
    auto nb = [](long long n, int t) { return (int)((n + t - 1) / t); };

    // prep (copy_x + weight splits + edge counting)
    k_prep<<<PREP_CNT, T>>>(x, Wcheb, Wg1, Wg2, ei);

    // CSR build (fused dinv+scan, then fill)
    k_dinv_scan<<<40, T>>>();
    k_fill<<<nb(EE, T), T>>>(ei);

    // Cheb recurrence
    k_gather_cheb<<<nb(NN, 8), 256>>>(0, 1 * F_IN, 0, 0, 1);
    k_gather_cheb<<<nb(NN, 8), 256>>>(1 * F_IN, 2 * F_IN, 0 * F_IN, 1, 1);
    k_gather_cheb<<<nb(NN, 8), 256>>>(2 * F_IN, 3 * F_IN, 1 * F_IN, 1, 1);
    k_gather_cheb<<<nb(NN, 8), 256>>>(3 * F_IN, 4 * F_IN, 2 * F_IN, 1, 0);

    // GEMM1: h1 = relu(TX @ Wcheb + b) -> fp32 [NN, C1D]
    k_gemm_tc<<<dim3(C1D / GBN, nb(NN, GBM)), 256, GEMM_SMEM>>>(
        ptxh, ptxl, pwh + WC_OFF, pwl + WC_OFF, bcheb, nullptr, pA, NN, TXW, C1D, 3);

    // GCN1
    k_gather_gcn_pre<C1D><<<nb(NN, 8), 256>>>(pA, paxh, paxl);
    k_gemm_tc<<<dim3(C2D / GBN, nb(NN, GBM)), 256, GEMM_SMEM>>>(
        paxh, paxl, pwh + W1_OFF, pwl + W1_OFF, bg1, nullptr, pB, NN, C1D, C2D, 3);

    // GCN2 (+ fused gate logits into g_e)
    k_gather_gcn_pre<C2D><<<nb(NN, 4), 256>>>(pB, paxh, paxl);
    k_gemm_tc<<<dim3(C3D / GBN, nb(NN, GBM)), 256, GEMM_SMEM>>>(
        paxh, paxl, pwh + W2_OFF, pwl + W2_OFF, bg2, wgate, pA, NN, C2D, C3D, 3 | 4);

    // fused pooling + FC + log_softmax (+ counter/barrier zeroing)
    k_pool_fused<<<GG + nb(NN, T), 256>>>(batch, pA, Wfc, bfc, out);
}

// round 17
// speedup vs baseline: 1.0333x; 1.0333x over previous
#include <cuda_runtime.h>
#include <cuda_bf16.h>

#define NN 10000
#define EE 160000
#define GG 64
#define F_IN 128
#define C1D 128
#define C2D 256
#define C3D 512
#define KCH 5
#define NCLS 10
#define TXW (KCH * F_IN)   // 640
#define NEG_INF (-3.402823466e38f)

typedef __nv_bfloat16 bf16;
typedef __nv_bfloat162 bf162;

// ---------------- scratch (device globals; zero-initialized at load) --------
__device__ int   g_cnt_in[NN];
__device__ int   g_cnt_out[NN];
__device__ int   g_cursor[NN];
__device__ int   g_bar;
__device__ int   g_bsum[40];
__device__ int   g_row_ptr[NN + 1];
__device__ int   g_col[EE];
__device__ float g_dinv_cheb[NN];
__device__ float g_dinv_gcn[NN];
__device__ float g_e[NN];
__device__ float g_TX[(size_t)NN * TXW];
__device__ float g_bufA[(size_t)NN * C3D];
__device__ float g_bufB[(size_t)NN * C2D];

__device__ __align__(16) bf16 g_txh[(size_t)NN * TXW];
__device__ __align__(16) bf16 g_txl[(size_t)NN * TXW];
__device__ __align__(16) bf16 g_axh[(size_t)NN * C2D];
__device__ __align__(16) bf16 g_axl[(size_t)NN * C2D];
#define WC_OFF 0
#define W1_OFF (C1D * TXW)
#define W2_OFF (W1_OFF + C2D * C1D)
#define W_TOT  (W2_OFF + C3D * C2D)
__device__ __align__(16) bf16 g_wth[W_TOT];
__device__ __align__(16) bf16 g_wtl[W_TOT];

// ---------------- helpers ---------------------------------------------------
__device__ __forceinline__ void split_bf16(float v, bf16& hi, bf16& lo) {
    hi = __float2bfloat16(v);
    lo = __float2bfloat16(v - __bfloat162float(hi));
}

__device__ __forceinline__ void write_split4(bf16* hbase, bf16* lbase, size_t idx, float4 v) {
    bf16 h0, l0, h1, l1, h2, l2, h3, l3;
    split_bf16(v.x, h0, l0); split_bf16(v.y, h1, l1);
    split_bf16(v.z, h2, l2); split_bf16(v.w, h3, l3);
    *(bf162*)(hbase + idx)     = bf162(h0, h1);
    *(bf162*)(hbase + idx + 2) = bf162(h2, h3);
    *(bf162*)(lbase + idx)     = bf162(l0, l1);
    *(bf162*)(lbase + idx + 2) = bf162(l2, l3);
}

__device__ __forceinline__ void cp16(void* sm, const void* gm) {
    unsigned sa = (unsigned)__cvta_generic_to_shared(sm);
    asm volatile("cp.async.cg.shared.global [%0], [%1], 16;" :: "r"(sa), "l"(gm));
}

// ---------------- fused prep: copy_x + 3 weight splits + edge counting -------
#define PREP_CX   1250
#define PREP_WC   (PREP_CX + 320)
#define PREP_W1   (PREP_WC + 128)
#define PREP_W2   (PREP_W1 + 512)
#define PREP_CNT  (PREP_W2 + 625)
__global__ void k_prep(const float* __restrict__ x, const float* __restrict__ Wc,
                       const float* __restrict__ W1, const float* __restrict__ W2,
                       const int* __restrict__ ei) {
    int b = blockIdx.x, tid = threadIdx.x;
    if (b < PREP_CX) {
        int idx = b * 256 + tid;
        int n = idx >> 5, j = idx & 31;
        float4 v = ((const float4*)x)[(size_t)n * 32 + j];
        size_t o = (size_t)n * TXW + j * 4;
        *((float4*)(g_TX + o)) = v;
        write_split4(g_txh, g_txl, o, v);
    } else if (b < PREP_WC) {
        int idx = (b - PREP_CX) * 256 + tid;
        int k = idx / C1D, n = idx - k * C1D;
        bf16 hi, lo; split_bf16(Wc[idx], hi, lo);
        g_wth[WC_OFF + (size_t)n * TXW + k] = hi;
        g_wtl[WC_OFF + (size_t)n * TXW + k] = lo;
    } else if (b < PREP_W1) {
        int idx = (b - PREP_WC) * 256 + tid;
        int k = idx / C2D, n = idx - k * C2D;
        bf16 hi, lo; split_bf16(W1[idx], hi, lo);
        g_wth[W1_OFF + (size_t)n * C1D + k] = hi;
        g_wtl[W1_OFF + (size_t)n * C1D + k] = lo;
    } else if (b < PREP_W2) {
        int idx = (b - PREP_W1) * 256 + tid;
        int k = idx / C3D, n = idx - k * C3D;
        bf16 hi, lo; split_bf16(W2[idx], hi, lo);
        g_wth[W2_OFF + (size_t)n * C2D + k] = hi;
        g_wtl[W2_OFF + (size_t)n * C2D + k] = lo;
    } else {
        int e = (b - PREP_W2) * 256 + tid;
        if (e < EE) {
            atomicAdd(&g_cnt_out[ei[e]], 1);
            atomicAdd(&g_cnt_in[ei[EE + e]], 1);
        }
    }
}

// ---------------- fused dinv + scan (40 blocks, spin barrier) ----------------
__global__ void k_dinv_scan() {
    __shared__ int red[256];
    __shared__ int sm_bs[40];
    __shared__ int sm_ws[8];
    int tid = threadIdx.x, lane = tid & 31, warp = tid >> 5;
    int i = blockIdx.x * 256 + tid;

    int ci = 0;
    if (i < NN) {
        int oc = g_cnt_out[i];
        ci = g_cnt_in[i];
        g_dinv_cheb[i] = oc > 0 ? rsqrtf((float)oc) : 0.f;
        g_dinv_gcn[i]  = rsqrtf((float)(ci + 1));
    }
    red[tid] = ci;
    __syncthreads();
    #pragma unroll
    for (int s = 128; s > 0; s >>= 1) {
        if (tid < s) red[tid] += red[tid + s];
        __syncthreads();
    }
    if (tid == 0) g_bsum[blockIdx.x] = red[0];

    if (tid == 0) {
        __threadfence();
        atomicAdd(&g_bar, 1);
        while (atomicAdd(&g_bar, 0) < 40) {}
    }
    __syncthreads();

    if (tid < 40) sm_bs[tid] = g_bsum[tid];
    __syncthreads();
    if (tid == 0) {
        int acc = 0;
        for (int b = 0; b < 40; b++) { int v = sm_bs[b]; sm_bs[b] = acc; acc += v; }
    }
    __syncthreads();
    int v = (i < NN) ? g_cnt_in[i] : 0;
    int inc = v;
    #pragma unroll
    for (int o = 1; o < 32; o <<= 1) {
        int t = __shfl_up_sync(0xffffffffu, inc, o);
        if (lane >= o) inc += t;
    }
    if (lane == 31) sm_ws[warp] = inc;
    __syncthreads();
    if (tid == 0) {
        int acc = 0;
        #pragma unroll
        for (int w = 0; w < 8; w++) { int t = sm_ws[w]; sm_ws[w] = acc; acc += t; }
    }
    __syncthreads();
    int excl = sm_bs[blockIdx.x] + sm_ws[warp] + inc - v;
    if (i < NN) g_row_ptr[i] = excl;
    if (i == NN - 1) g_row_ptr[NN] = excl + v;
}

__global__ void k_fill(const int* __restrict__ ei) {
    int e = blockIdx.x * blockDim.x + threadIdx.x;
    if (e < NN) g_e[e] = 0.f;
    if (e >= EE) return;
    int s = ei[e];
    int d = ei[EE + e];
    int pos = g_row_ptr[d] + atomicAdd(&g_cursor[d], 1);
    g_col[pos] = s;
}

// ---------------- Cheb gather (pipelined index prefetch, MLP 8) --------------
__global__ void k_gather_cheb(int src_off, int dst_off, int tx0_off, int mode, int store_f32) {
    int n = blockIdx.x * 8 + (threadIdx.x >> 5);
    int j = threadIdx.x & 31;
    if (n >= NN) return;
    int beg = g_row_ptr[n], end = g_row_ptr[n + 1];
    float4 acc = {0.f, 0.f, 0.f, 0.f};
    int nb = (end - beg) >> 3;           // full 8-edge batches
    int r = beg;
    int s[8], sn[8];
    if (nb > 0) {
        #pragma unroll
        for (int u = 0; u < 8; u++) s[u] = __ldg(&g_col[r + u]);
    }
    for (int b = 0; b < nb; b++, r += 8) {
        if (b + 1 < nb) {
            #pragma unroll
            for (int u = 0; u < 8; u++) sn[u] = __ldg(&g_col[r + 8 + u]);
        }
        float w[8];
        #pragma unroll
        for (int u = 0; u < 8; u++) w[u] = __ldg(&g_dinv_cheb[s[u]]);
        float4 h[8];
        #pragma unroll
        for (int u = 0; u < 8; u++)
            h[u] = *(const float4*)(g_TX + (size_t)s[u] * TXW + src_off + j * 4);
        #pragma unroll
        for (int u = 0; u < 8; u++) {
            acc.x += w[u] * h[u].x; acc.y += w[u] * h[u].y;
            acc.z += w[u] * h[u].z; acc.w += w[u] * h[u].w;
        }
        #pragma unroll
        for (int u = 0; u < 8; u++) s[u] = sn[u];
    }
    for (; r < end; r++) {
        int sc  = __ldg(&g_col[r]);
        float w = __ldg(&g_dinv_cheb[sc]);
        float4 h = *(const float4*)(g_TX + (size_t)sc * TXW + src_off + j * 4);
        acc.x += w * h.x; acc.y += w * h.y; acc.z += w * h.z; acc.w += w * h.w;
    }
    float f = -g_dinv_cheb[n] * (mode ? 2.f : 1.f);
    float4 res;
    if (mode) {
        float4 t0 = *(const float4*)(g_TX + (size_t)n * TXW + tx0_off + j * 4);
        res.x = fmaf(f, acc.x, -t0.x); res.y = fmaf(f, acc.y, -t0.y);
        res.z = fmaf(f, acc.z, -t0.z); res.w = fmaf(f, acc.w, -t0.w);
    } else {
        res.x = f * acc.x; res.y = f * acc.y; res.z = f * acc.z; res.w = f * acc.w;
    }
    size_t o = (size_t)n * TXW + dst_off + j * 4;
    if (store_f32) *(float4*)(g_TX + o) = res;
    write_split4(g_txh, g_txl, o, res);
}

// ---------------- GCN gather (pipelined index prefetch) -----------------------
template <int C>
__global__ void k_gather_gcn_pre(const float* __restrict__ h,
                                 bf16* __restrict__ oh, bf16* __restrict__ ol) {
    constexpr int TPN = C / 4;
    constexpr int NPB = 256 / TPN;
    int local = threadIdx.x / TPN;
    int j     = threadIdx.x % TPN;
    int n = blockIdx.x * NPB + local;
    if (n >= NN) return;
    const float4* h4 = (const float4*)h;
    int beg = g_row_ptr[n], end = g_row_ptr[n + 1];
    float4 acc = {0.f, 0.f, 0.f, 0.f};
    int nb = (end - beg) >> 3;
    int r = beg;
    int s[8], sn[8];
    if (nb > 0) {
        #pragma unroll
        for (int u = 0; u < 8; u++) s[u] = __ldg(&g_col[r + u]);
    }
    for (int b = 0; b < nb; b++, r += 8) {
        if (b + 1 < nb) {
            #pragma unroll
            for (int u = 0; u < 8; u++) sn[u] = __ldg(&g_col[r + 8 + u]);
        }
        float w[8];
        #pragma unroll
        for (int u = 0; u < 8; u++) w[u] = __ldg(&g_dinv_gcn[s[u]]);
        float4 hv[8];
        #pragma unroll
        for (int u = 0; u < 8; u++) hv[u] = h4[(size_t)s[u] * TPN + j];
        #pragma unroll
        for (int u = 0; u < 8; u++) {
            acc.x += w[u] * hv[u].x; acc.y += w[u] * hv[u].y;
            acc.z += w[u] * hv[u].z; acc.w += w[u] * hv[u].w;
        }
        #pragma unroll
        for (int u = 0; u < 8; u++) s[u] = sn[u];
    }
    for (; r < end; r++) {
        int sc  = __ldg(&g_col[r]);
        float w = __ldg(&g_dinv_gcn[sc]);
        float4 hv = h4[(size_t)sc * TPN + j];
        acc.x += w * hv.x; acc.y += w * hv.y; acc.z += w * hv.z; acc.w += w * hv.w;
    }
    float di = g_dinv_gcn[n];
    float sw = di * di;
    float4 self = h4[(size_t)n * TPN + j];
    float4 res;
    res.x = fmaf(di, acc.x, sw * self.x);
    res.y = fmaf(di, acc.y, sw * self.y);
    res.z = fmaf(di, acc.z, sw * self.z);
    res.w = fmaf(di, acc.w, sw * self.w);
    write_split4(oh, ol, (size_t)n * C + j * 4, res);
}

// ---------------- bf16x3 tensor-core GEMM, double-buffered cp.async -----------
#define GBM 128
#define GBN 64
#define GBK 32
#define SPAD 8
#define ROWW (GBK + SPAD)
#define A_ELEMS (GBM * ROWW)
#define B_ELEMS (GBN * ROWW)
#define STAGE_ELEMS (2 * A_ELEMS + 2 * B_ELEMS)
#define GEMM_SMEM (2 * STAGE_ELEMS * 2)

__device__ __forceinline__ void mma_bf16(float c[4], unsigned a0, unsigned a1,
                                         unsigned a2, unsigned a3,
                                         unsigned b0, unsigned b1) {
    asm volatile(
        "mma.sync.aligned.m16n8k16.row.col.f32.bf16.bf16.f32 "
        "{%0,%1,%2,%3}, {%4,%5,%6,%7}, {%8,%9}, {%0,%1,%2,%3};"
        : "+f"(c[0]), "+f"(c[1]), "+f"(c[2]), "+f"(c[3])
        : "r"(a0), "r"(a1), "r"(a2), "r"(a3), "r"(b0), "r"(b1));
}

__global__ __launch_bounds__(256, 2)
void k_gemm_tc(const bf16* __restrict__ Agh, const bf16* __restrict__ Agl,
               const bf16* __restrict__ Bgh, const bf16* __restrict__ Bgl,
               const float* __restrict__ bias, const float* __restrict__ wgate,
               float* __restrict__ Cf,
               int M, int Kd, int Nd, int flags) {
    extern __shared__ bf16 sm[];
    int tid = threadIdx.x;
    int wid = tid >> 5, lane = tid & 31;
    int wm = wid >> 1, wn = wid & 1;
    int g = lane >> 2, tg = lane & 3;
    int brow = blockIdx.y * GBM;
    int bcol = blockIdx.x * GBN;

    float acc[2][4][4];
    #pragma unroll
    for (int a = 0; a < 2; a++)
        #pragma unroll
        for (int b = 0; b < 4; b++)
            #pragma unroll
            for (int c = 0; c < 4; c++) acc[a][b][c] = 0.f;

    int sr = tid >> 2;
    int sq = (tid & 3) * 8;

    auto AH = [&](int st) { return sm + st * STAGE_ELEMS; };
    auto AL = [&](int st) { return sm + st * STAGE_ELEMS + A_ELEMS; };
    auto BH = [&](int st) { return sm + st * STAGE_ELEMS + 2 * A_ELEMS; };
    auto BL = [&](int st) { return sm + st * STAGE_ELEMS + 2 * A_ELEMS + B_ELEMS; };

    auto load_tile = [&](int k0, int st) {
        #pragma unroll
        for (int i = 0; i < 2; i++) {
            int r = sr + i * 64;
            int gr = min(brow + r, M - 1);
            size_t go = (size_t)gr * Kd + k0 + sq;
            cp16(AH(st) + r * ROWW + sq, Agh + go);
            cp16(AL(st) + r * ROWW + sq, Agl + go);
        }
        size_t go = (size_t)(bcol + sr) * Kd + k0 + sq;
        cp16(BH(st) + sr * ROWW + sq, Bgh + go);
        cp16(BL(st) + sr * ROWW + sq, Bgl + go);
    };

    int nt = Kd / GBK;
    load_tile(0, 0);
    asm volatile("cp.async.commit_group;");

    for (int t = 0; t < nt; t++) {
        if (t + 1 < nt) {
            load_tile((t + 1) * GBK, (t + 1) & 1);
            asm volatile("cp.async.commit_group;");
            asm volatile("cp.async.wait_group 1;");
        } else {
            asm volatile("cp.async.wait_group 0;");
        }
        __syncthreads();

        int st = t & 1;
        const bf16* ah_b = AH(st);
        const bf16* al_b = AL(st);
        const bf16* bh_b = BH(st);
        const bf16* bl_b = BL(st);

        #pragma unroll
        for (int ks = 0; ks < 2; ks++) {
            int kb = ks * 16;
            unsigned ah[2][4], al[2][4];
            #pragma unroll
            for (int mf = 0; mf < 2; mf++) {
                int row = wm * 32 + mf * 16;
                ah[mf][0] = *(const unsigned*)(ah_b + (row + g) * ROWW + kb + 2 * tg);
                ah[mf][1] = *(const unsigned*)(ah_b + (row + g + 8) * ROWW + kb + 2 * tg);
                ah[mf][2] = *(const unsigned*)(ah_b + (row + g) * ROWW + kb + 2 * tg + 8);
                ah[mf][3] = *(const unsigned*)(ah_b + (row + g + 8) * ROWW + kb + 2 * tg + 8);
                al[mf][0] = *(const unsigned*)(al_b + (row + g) * ROWW + kb + 2 * tg);
                al[mf][1] = *(const unsigned*)(al_b + (row + g + 8) * ROWW + kb + 2 * tg);
                al[mf][2] = *(const unsigned*)(al_b + (row + g) * ROWW + kb + 2 * tg + 8);
                al[mf][3] = *(const unsigned*)(al_b + (row + g + 8) * ROWW + kb + 2 * tg + 8);
            }
            #pragma unroll
            for (int nf = 0; nf < 4; nf++) {
                int nn = wn * 32 + nf * 8 + g;
                unsigned bh0 = *(const unsigned*)(bh_b + nn * ROWW + kb + 2 * tg);
                unsigned bh1 = *(const unsigned*)(bh_b + nn * ROWW + kb + 2 * tg + 8);
                unsigned bl0 = *(const unsigned*)(bl_b + nn * ROWW + kb + 2 * tg);
                unsigned bl1 = *(const unsigned*)(bl_b + nn * ROWW + kb + 2 * tg + 8);
                #pragma unroll
                for (int mf = 0; mf < 2; mf++) {
                    mma_bf16(acc[mf][nf], ah[mf][0], ah[mf][1], ah[mf][2], ah[mf][3], bh0, bh1);
                    mma_bf16(acc[mf][nf], ah[mf][0], ah[mf][1], ah[mf][2], ah[mf][3], bl0, bl1);
                    mma_bf16(acc[mf][nf], al[mf][0], al[mf][1], al[mf][2], al[mf][3], bh0, bh1);
                }
            }
        }
        __syncthreads();
    }

    #pragma unroll
    for (int mf = 0; mf < 2; mf++) {
        int gr0 = brow + wm * 32 + mf * 16 + g;
        float lg0 = 0.f, lg1 = 0.f;
        #pragma unroll
        for (int nf = 0; nf < 4; nf++) {
            int gc = bcol + wn * 32 + nf * 8 + 2 * tg;
            float b0 = 0.f, b1 = 0.f;
            if (flags & 1) { b0 = bias[gc]; b1 = bias[gc + 1]; }
            float v0 = acc[mf][nf][0] + b0;
            float v1 = acc[mf][nf][1] + b1;
            float v2 = acc[mf][nf][2] + b0;
            float v3 = acc[mf][nf][3] + b1;
            if (flags & 2) {
                v0 = fmaxf(v0, 0.f); v1 = fmaxf(v1, 0.f);
                v2 = fmaxf(v2, 0.f); v3 = fmaxf(v3, 0.f);
            }
            if (flags & 4) {
                float w0 = wgate[gc], w1 = wgate[gc + 1];
                lg0 += v0 * w0 + v1 * w1;
                lg1 += v2 * w0 + v3 * w1;
            }
            if (gr0 < M)     *(float2*)(Cf + (size_t)gr0 * Nd + gc)       = make_float2(v0, v1);
            if (gr0 + 8 < M) *(float2*)(Cf + (size_t)(gr0 + 8) * Nd + gc) = make_float2(v2, v3);
        }
        if (flags & 4) {
            #pragma unroll
            for (int o = 1; o < 4; o <<= 1) {
                lg0 += __shfl_xor_sync(0xffffffffu, lg0, o);
                lg1 += __shfl_xor_sync(0xffffffffu, lg1, o);
            }
            if (tg == 0) {
                if (gr0 < M)     atomicAdd(&g_e[gr0], lg0);
                if (gr0 + 8 < M) atomicAdd(&g_e[gr0 + 8], lg1);
            }
        }
    }
}

// ---------------- fused attention pooling + FC + log_softmax ------------------
__global__ void k_pool_fused(const int* __restrict__ batch, const float* __restrict__ h,
                             const float* __restrict__ Wfc, const float* __restrict__ bfc,
                             float* __restrict__ out) {
    if (blockIdx.x >= GG) {
        int i = (blockIdx.x - GG) * 256 + threadIdx.x;
        if (i < NN) { g_cnt_in[i] = 0; g_cnt_out[i] = 0; g_cursor[i] = 0; }
        if (blockIdx.x == GG && threadIdx.x == 0) g_bar = 0;
        return;
    }
    int g = blockIdx.x;
    int tid = threadIdx.x, lane = tid & 31, warp = tid >> 5;
    __shared__ float sm_part[8][C3D / 4];
    __shared__ float sm_pool[C3D];
    __shared__ float sm_w[64];
    __shared__ float sm_scalar[3];
    __shared__ int   sm_range[2];

    if (tid == 0) {
        int lo = 0, hi = NN;
        while (lo < hi) { int mid = (lo + hi) >> 1; if (batch[mid] < g) lo = mid + 1; else hi = mid; }
        sm_range[0] = lo;
        lo = 0; hi = NN;
        while (lo < hi) { int mid = (lo + hi) >> 1; if (batch[mid] < g + 1) lo = mid + 1; else hi = mid; }
        sm_range[1] = lo;
        sm_scalar[0] = NEG_INF; sm_scalar[1] = 0.f;
    }
    __syncthreads();
    int start = sm_range[0], end = sm_range[1];

    float part[16];
    #pragma unroll
    for (int k = 0; k < 16; k++) part[k] = 0.f;

    for (int base = start; base < end; base += 64) {
        int cnt = min(64, end - base);
        if (tid < cnt) sm_w[tid] = g_e[base + tid];
        __syncthreads();
        if (warp == 0) {
            float v = NEG_INF;
            for (int i = lane; i < cnt; i += 32) v = fmaxf(v, sm_w[i]);
            #pragma unroll
            for (int o = 16; o; o >>= 1) v = fmaxf(v, __shfl_xor_sync(0xffffffffu, v, o));
            if (lane == 0) {
                float oldm = sm_scalar[0];
                float newm = fmaxf(oldm, v);
                sm_scalar[2] = expf(oldm - newm);
                sm_scalar[0] = newm;
            }
        }
        __syncthreads();
        float newm = sm_scalar[0], r = sm_scalar[2];
        if (tid < cnt) sm_w[tid] = expf(sm_w[tid] - newm);
        __syncthreads();
        if (warp == 0) {
            float v = 0.f;
            for (int i = lane; i < cnt; i += 32) v += sm_w[i];
            #pragma unroll
            for (int o = 16; o; o >>= 1) v += __shfl_xor_sync(0xffffffffu, v, o);
            if (lane == 0) sm_scalar[1] = sm_scalar[1] * r + v;
        }
        #pragma unroll
        for (int k = 0; k < 16; k++) part[k] *= r;
        for (int i = warp; i < cnt; i += 8) {
            float w = sm_w[i];
            const float* hr = h + (size_t)(base + i) * C3D;
            #pragma unroll
            for (int k = 0; k < 16; k++) part[k] = fmaf(w, hr[lane + k * 32], part[k]);
        }
        __syncthreads();
    }

    #pragma unroll
    for (int q = 0; q < 4; q++) {
        #pragma unroll
        for (int k = 0; k < 4; k++)
            sm_part[warp][k * 32 + lane] = part[q * 4 + k];
        __syncthreads();
        if (tid < 128) {
            float s = 0.f;
            #pragma unroll
            for (int w8 = 0; w8 < 8; w8++) s += sm_part[w8][tid];
            sm_pool[q * 128 + tid] = s;
        }
        __syncthreads();
    }

    float s = sm_scalar[1];
    float inv = (s > 0.f) ? 1.f / s : 0.f;
    if (warp == 0) {
        float lg[NCLS];
        #pragma unroll
        for (int c = 0; c < NCLS; c++) {
            float acc = 0.f;
            for (int k = lane; k < C3D; k += 32) acc += sm_pool[k] * Wfc[(size_t)k * NCLS + c];
            #pragma unroll
            for (int o = 16; o; o >>= 1) acc += __shfl_xor_sync(0xffffffffu, acc, o);
            lg[c] = acc * inv + bfc[c];
        }
        if (lane == 0) {
            float m = lg[0];
            #pragma unroll
            for (int c = 1; c < NCLS; c++) m = fmaxf(m, lg[c]);
            float ss = 0.f;
            #pragma unroll
            for (int c = 0; c < NCLS; c++) ss += expf(lg[c] - m);
            float lse = m + logf(ss);
            #pragma unroll
            for (int c = 0; c < NCLS; c++) out[(size_t)g * NCLS + c] = lg[c] - lse;
        }
    }
}

// ---------------- launch ------------------------------------------------------
extern "C" void kernel_launch(void* const* d_in, const int* in_sizes, int n_in,
                              void* d_out, int out_size) {
    const float* x      = (const float*)d_in[0];
    const int*   ei     = (const int*)d_in[1];
    const int*   batch  = (const int*)d_in[2];
    const float* Wcheb  = (const float*)d_in[3];
    const float* bcheb  = (const float*)d_in[4];
    const float* Wg1    = (const float*)d_in[5];
    const float* bg1    = (const float*)d_in[6];
    const float* Wg2    = (const float*)d_in[7];
    const float* bg2    = (const float*)d_in[8];
    const float* wgate  = (const float*)d_in[9];
    const float* Wfc    = (const float*)d_in[11];
    const float* bfc    = (const float*)d_in[12];
    float*       out    = (float*)d_out;

    float *pA, *pB;
    bf16 *ptxh, *ptxl, *paxh, *paxl, *pwh, *pwl;
    cudaGetSymbolAddress((void**)&pA,   g_bufA);
    cudaGetSymbolAddress((void**)&pB,   g_bufB);
    cudaGetSymbolAddress((void**)&ptxh, g_txh);
    cudaGetSymbolAddress((void**)&ptxl, g_txl);
    cudaGetSymbolAddress((void**)&paxh, g_axh);
    cudaGetSymbolAddress((void**)&paxl, g_axl);
    cudaGetSymbolAddress((void**)&pwh,  g_wth);
    cudaGetSymbolAddress((void**)&pwl,  g_wtl);

    static bool attr_set = false;
    if (!attr_set) {
        cudaFuncSetAttribute(k_gemm_tc, cudaFuncAttributeMaxDynamicSharedMemorySize, GEMM_SMEM);
        attr_set = true;
    }

    const int T = 256;
    auto nb = [](long long n, int t) { return (int)((n + t - 1) / t); };

    k_prep<<<PREP_CNT, T>>>(x, Wcheb, Wg1, Wg2, ei);
    k_dinv_scan<<<40, T>>>();
    k_fill<<<nb(EE, T), T>>>(ei);

    // Cheb recurrence (pipelined gathers)
    k_gather_cheb<<<nb(NN, 8), 256>>>(0, 1 * F_IN, 0, 0, 1);
    k_gather_cheb<<<nb(NN, 8), 256>>>(1 * F_IN, 2 * F_IN, 0 * F_IN, 1, 1);
    k_gather_cheb<<<nb(NN, 8), 256>>>(2 * F_IN, 3 * F_IN, 1 * F_IN, 1, 1);
    k_gather_cheb<<<nb(NN, 8), 256>>>(3 * F_IN, 4 * F_IN, 2 * F_IN, 1, 0);

    // GEMM1
    k_gemm_tc<<<dim3(C1D / GBN, nb(NN, GBM)), 256, GEMM_SMEM>>>(
        ptxh, ptxl, pwh + WC_OFF, pwl + WC_OFF, bcheb, nullptr, pA, NN, TXW, C1D, 3);

    // GCN1
    k_gather_gcn_pre<C1D><<<nb(NN, 8), 256>>>(pA, paxh, paxl);
    k_gemm_tc<<<dim3(C2D / GBN, nb(NN, GBM)), 256, GEMM_SMEM>>>(
        paxh, paxl, pwh + W1_OFF, pwl + W1_OFF, bg1, nullptr, pB, NN, C1D, C2D, 3);

    // GCN2 (+ fused gate logits)
    k_gather_gcn_pre<C2D><<<nb(NN, 4), 256>>>(pB, paxh, paxl);
    k_gemm_tc<<<dim3(C3D / GBN, nb(NN, GBM)), 256, GEMM_SMEM>>>(
        paxh, paxl, pwh + W2_OFF, pwl + W2_OFF, bg2, wgate, pA, NN, C2D, C3D, 3 | 4);

    // fused pooling + FC + log_softmax
    k_pool_fused<<<GG + nb(NN, T), 256>>>(batch, pA, Wfc, bfc, out);
}